// round 1
// baseline (speedup 1.0000x reference)
#include <cuda_runtime.h>
#include <math.h>

// Problem constants
#define BT_  16384   // B*T = 64*256
#define F_   64
#define E_   64
#define H_   8
#define P_   512
#define K_   1024    // 2 * F * H  (both branches concatenated)

// Scratch (static device globals — no runtime allocation)
__device__ float g_W[K_ * P_];       // folded weights [K, P]  (2 MB)
__device__ float g_Hbuf[BT_ * K_];   // tanh activations [BT, K] (64 MB)
__device__ float g_bias[P_];         // bx + bt

// ---------------------------------------------------------------------------
// Kernel 1: fold E dimension into weights.
//   W[branch*512 + f*8 + h][p] = sum_e w2[f,h,e] * wproj[(f*64+e), p]
// grid (F, 2), block 512 (one thread per p)
// ---------------------------------------------------------------------------
__global__ void precompute_W(const float* __restrict__ w2v, const float* __restrict__ wx,
                             const float* __restrict__ w2t, const float* __restrict__ wt,
                             const float* __restrict__ bx,  const float* __restrict__ bt) {
    const int f      = blockIdx.x;   // 0..63
    const int branch = blockIdx.y;   // 0..1
    const int p      = threadIdx.x;  // 0..511

    const float* __restrict__ w2 = branch ? w2t : w2v;
    const float* __restrict__ wp = branch ? wt  : wx;

    __shared__ float s_w2[H_ * E_];  // 512 floats: w2[f, :, :]
    if (p < H_ * E_) s_w2[p] = w2[f * H_ * E_ + p];
    __syncthreads();

    float acc[H_];
#pragma unroll
    for (int h = 0; h < H_; h++) acc[h] = 0.f;

    for (int e = 0; e < E_; e++) {
        const float w = wp[(size_t)(f * E_ + e) * P_ + p];
#pragma unroll
        for (int h = 0; h < H_; h++) acc[h] = fmaf(s_w2[h * E_ + e], w, acc[h]);
    }
#pragma unroll
    for (int h = 0; h < H_; h++)
        g_W[(size_t)(branch * 512 + f * H_ + h) * P_ + p] = acc[h];

    if (f == 0 && branch == 0) g_bias[p] = bx[p] + bt[p];
}

// ---------------------------------------------------------------------------
// Kernel 2: activation materialization.
//   Hbuf[bt, k] with k = branch*512 + f*8 + h
//   = tanh(inp[bt,f] * w1[f,h] + b1[f,h])
// ---------------------------------------------------------------------------
__global__ void tanh_act(const float* __restrict__ x,   const float* __restrict__ tm,
                         const float* __restrict__ w1v, const float* __restrict__ b1v,
                         const float* __restrict__ w1t, const float* __restrict__ b1t) {
    const int idx = blockIdx.x * blockDim.x + threadIdx.x;  // over BT_*K_
    const int bt     = idx >> 10;        // / 1024
    const int k      = idx & 1023;
    const int branch = k >> 9;
    const int fk     = k & 511;          // f*8 + h
    const int f      = fk >> 3;

    const float inp = (branch ? tm  : x  )[bt * F_ + f];
    const float w   = (branch ? w1t : w1v)[fk];
    const float b   = (branch ? b1t : b1v)[fk];
    g_Hbuf[idx] = tanhf(fmaf(inp, w, b));
}

// ---------------------------------------------------------------------------
// Kernel 3: C[16384,512] = Hbuf[16384,1024] @ W[1024,512] + bias
// Classic SIMT tiled GEMM: BM=128, BN=128, BK=16, 256 threads, 8x8 micro-tile
// ---------------------------------------------------------------------------
#define BM 128
#define BN 128
#define BK 16
#define TM 8
#define TN 8

__global__ void __launch_bounds__(256, 2) gemm_out(float* __restrict__ C) {
    __shared__ float As[BK][BM];   // A transposed in smem
    __shared__ float Bs[BK][BN];

    const int bm  = blockIdx.y * BM;
    const int bn  = blockIdx.x * BN;
    const int tid = threadIdx.x;
    const int tmr = (tid / 16) * TM;   // row offset within tile
    const int tnc = (tid % 16) * TN;   // col offset within tile

    // Global load mapping (float4):
    // A tile: 128 rows x 16 cols = 512 float4 -> 2 per thread
    const int a_row  = tid / 4;          // 0..63, plus +64
    const int a_col  = (tid % 4) * 4;    // 0,4,8,12
    // B tile: 16 rows x 128 cols = 512 float4 -> 2 per thread
    const int b_row  = tid / 32;         // 0..7, plus +8
    const int b_col  = (tid % 32) * 4;

    const float* __restrict__ A = g_Hbuf;
    const float* __restrict__ B = g_W;

    float acc[TM][TN] = {};

    for (int k0 = 0; k0 < K_; k0 += BK) {
#pragma unroll
        for (int r = 0; r < 2; r++) {
            const int row = a_row + r * 64;
            const float4 v = *(const float4*)&A[(size_t)(bm + row) * K_ + k0 + a_col];
            As[a_col + 0][row] = v.x;
            As[a_col + 1][row] = v.y;
            As[a_col + 2][row] = v.z;
            As[a_col + 3][row] = v.w;
        }
#pragma unroll
        for (int r = 0; r < 2; r++) {
            const int row = b_row + r * 8;
            *(float4*)&Bs[row][b_col] =
                *(const float4*)&B[(size_t)(k0 + row) * P_ + bn + b_col];
        }
        __syncthreads();

#pragma unroll
        for (int k = 0; k < BK; k++) {
            float a[TM], b[TN];
#pragma unroll
            for (int i = 0; i < TM; i += 4) *(float4*)&a[i] = *(const float4*)&As[k][tmr + i];
#pragma unroll
            for (int j = 0; j < TN; j += 4) *(float4*)&b[j] = *(const float4*)&Bs[k][tnc + j];
#pragma unroll
            for (int i = 0; i < TM; i++)
#pragma unroll
                for (int j = 0; j < TN; j++)
                    acc[i][j] = fmaf(a[i], b[j], acc[i][j]);
        }
        __syncthreads();
    }

    // Epilogue: add fused bias, store
    float bias[TN];
#pragma unroll
    for (int j = 0; j < TN; j += 4) *(float4*)&bias[j] = *(const float4*)&g_bias[bn + tnc + j];

#pragma unroll
    for (int i = 0; i < TM; i++) {
#pragma unroll
        for (int j = 0; j < TN; j += 4) {
            float4 v;
            v.x = acc[i][j + 0] + bias[j + 0];
            v.y = acc[i][j + 1] + bias[j + 1];
            v.z = acc[i][j + 2] + bias[j + 2];
            v.w = acc[i][j + 3] + bias[j + 3];
            *(float4*)&C[(size_t)(bm + tmr + i) * P_ + bn + tnc + j] = v;
        }
    }
}

// ---------------------------------------------------------------------------
// Launch
// Input order (metadata): x, time, w1v, b1v, w2v, w1t, b1t, w2t, wx, bx, wt, bt
// ---------------------------------------------------------------------------
extern "C" void kernel_launch(void* const* d_in, const int* in_sizes, int n_in,
                              void* d_out, int out_size) {
    const float* x    = (const float*)d_in[0];
    const float* tmi  = (const float*)d_in[1];
    const float* w1v  = (const float*)d_in[2];
    const float* b1v  = (const float*)d_in[3];
    const float* w2v  = (const float*)d_in[4];
    const float* w1t  = (const float*)d_in[5];
    const float* b1t  = (const float*)d_in[6];
    const float* w2t  = (const float*)d_in[7];
    const float* wx   = (const float*)d_in[8];
    const float* bx   = (const float*)d_in[9];
    const float* wt   = (const float*)d_in[10];
    const float* bt   = (const float*)d_in[11];
    float* out = (float*)d_out;

    // 1) fold E into weights: W [1024, 512], plus bias
    precompute_W<<<dim3(F_, 2), P_>>>(w2v, wx, w2t, wt, bx, bt);

    // 2) tanh activations: Hbuf [16384, 1024]
    tanh_act<<<(BT_ * K_) / 256, 256>>>(x, tmi, w1v, b1v, w1t, b1t);

    // 3) GEMM + bias -> out [16384, 512]
    gemm_out<<<dim3(P_ / BN, BT_ / BM), 256>>>(out);
}

// round 3
// speedup vs baseline: 2.3403x; 2.3403x over previous
#include <cuda_runtime.h>
#include <math.h>
#include <stdint.h>

// Problem constants
#define BT_  16384   // B*T
#define F_   64
#define E_   64
#define H_   8
#define P_   512
#define K_   1024    // 2*F*H

// GEMM tiling
#define BM 128
#define BN 128
#define BK 32
#define NT (K_ / BK)       // 32 k-tiles
#define NSTAGE 3
#define LDS_STRIDE 36                       // floats per smem row (32 + 4 pad)
#define STAGE_F ((BM + BN) * LDS_STRIDE)    // floats per stage = 9216
#define SMEM_BYTES (NSTAGE * STAGE_F * 4)   // 110592

// Scratch (static device globals). Both hold tf32-rounded values in
// k-interleaved order: within each k8 block, storage order is
// [k0,k4,k1,k5,k2,k6,k3,k7]  (pos(k) = (k%4)*2 + k/4).
__device__ float g_Wt[P_ * K_];      // folded weights, [P][K] (2MB)
__device__ float g_Hbuf[BT_ * K_];   // tanh activations [BT][K] (64MB)
__device__ float g_bias[P_];

// ---------------------------------------------------------------------------
// helpers
// ---------------------------------------------------------------------------
__device__ __forceinline__ uint32_t smem_u32(const void* p) {
    uint32_t a;
    asm("{ .reg .u64 t; cvta.to.shared.u64 t, %1; cvt.u32.u64 %0, t; }" : "=r"(a) : "l"(p));
    return a;
}

__device__ __forceinline__ float to_tf32(float x) {
    uint32_t u;
    asm("cvt.rna.tf32.f32 %0, %1;" : "=r"(u) : "f"(x));
    return __uint_as_float(u);
}

__device__ __forceinline__ void cp16(uint32_t dst, const void* src) {
    asm volatile("cp.async.cg.shared.global [%0], [%1], 16;" :: "r"(dst), "l"(src) : "memory");
}

#define CP_COMMIT()  asm volatile("cp.async.commit_group;" ::: "memory")
#define CP_WAIT(n)   asm volatile("cp.async.wait_group %0;" :: "n"(n) : "memory")

__device__ __forceinline__ void mma_tf32(float c[4], const uint32_t a[4], const uint32_t b[2]) {
    asm volatile(
        "mma.sync.aligned.m16n8k8.row.col.f32.tf32.tf32.f32 "
        "{%0,%1,%2,%3}, {%4,%5,%6,%7}, {%8,%9}, {%0,%1,%2,%3};"
        : "+f"(c[0]), "+f"(c[1]), "+f"(c[2]), "+f"(c[3])
        : "r"(a[0]), "r"(a[1]), "r"(a[2]), "r"(a[3]), "r"(b[0]), "r"(b[1]));
}

// ---------------------------------------------------------------------------
// Kernel 1: fold E into weights; write TRANSPOSED, tf32-rounded, k-interleaved
//   g_Wt[p][kpos], kpos base = branch*512 + f*8, order [0,4,1,5,2,6,3,7]
// grid (F, 2), block 512
// ---------------------------------------------------------------------------
__global__ void precompute_W(const float* __restrict__ w2v, const float* __restrict__ wx,
                             const float* __restrict__ w2t, const float* __restrict__ wt,
                             const float* __restrict__ bx,  const float* __restrict__ bt) {
    const int f      = blockIdx.x;
    const int branch = blockIdx.y;
    const int p      = threadIdx.x;

    const float* __restrict__ w2 = branch ? w2t : w2v;
    const float* __restrict__ wp = branch ? wt  : wx;

    __shared__ float s_w2[H_ * E_];
    if (p < H_ * E_) s_w2[p] = w2[f * H_ * E_ + p];
    __syncthreads();

    float acc[H_];
#pragma unroll
    for (int h = 0; h < H_; h++) acc[h] = 0.f;

    for (int e = 0; e < E_; e++) {
        const float w = wp[(size_t)(f * E_ + e) * P_ + p];
#pragma unroll
        for (int h = 0; h < H_; h++) acc[h] = fmaf(s_w2[h * E_ + e], w, acc[h]);
    }
    const size_t base = (size_t)p * K_ + branch * 512 + f * H_;
    // interleaved order: pos -> h = (pos%2)*4 + pos/2
    float4 v0 = make_float4(to_tf32(acc[0]), to_tf32(acc[4]), to_tf32(acc[1]), to_tf32(acc[5]));
    float4 v1 = make_float4(to_tf32(acc[2]), to_tf32(acc[6]), to_tf32(acc[3]), to_tf32(acc[7]));
    *(float4*)&g_Wt[base]     = v0;
    *(float4*)&g_Wt[base + 4] = v1;

    if (f == 0 && branch == 0) g_bias[p] = bx[p] + bt[p];
}

// ---------------------------------------------------------------------------
// Kernel 2: tanh activations -> g_Hbuf [BT][K] tf32-rounded, k-interleaved
// ---------------------------------------------------------------------------
__global__ void tanh_act(const float* __restrict__ x,   const float* __restrict__ tm,
                         const float* __restrict__ w1v, const float* __restrict__ b1v,
                         const float* __restrict__ w1t, const float* __restrict__ b1t) {
    const int idx    = blockIdx.x * blockDim.x + threadIdx.x;  // kpos-space index
    const int bt     = idx >> 10;
    const int kpos   = idx & 1023;
    const int branch = kpos >> 9;
    const int fk     = kpos & 511;
    const int f      = fk >> 3;
    const int posn   = fk & 7;
    const int h      = ((posn & 1) << 2) | (posn >> 1);  // invert interleave

    const float inp = (branch ? tm  : x  )[bt * F_ + f];
    const float w   = (branch ? w1t : w1v)[f * H_ + h];
    const float b   = (branch ? b1t : b1v)[f * H_ + h];
    g_Hbuf[idx] = to_tf32(tanhf(fmaf(inp, w, b)));
}

// ---------------------------------------------------------------------------
// Kernel 3: C[16384,512] = Hbuf @ Wt^T + bias, tf32 mma.sync
// grid (P/BN=4, BT/BM=128), 256 threads (8 warps as 2m x 4n)
// ---------------------------------------------------------------------------
__device__ __forceinline__ void fill_stage(uint32_t sbase, int stage, int kt, int bm, int bn, int tid) {
    const uint32_t a0 = sbase + (uint32_t)(stage * STAGE_F) * 4u;
    const uint32_t b0 = a0 + (uint32_t)(BM * LDS_STRIDE) * 4u;
    const int k0 = kt * BK;
    // A: 128 rows x 8 chunks of 16B = 1024 chunks; 4 per thread
#pragma unroll
    for (int i = 0; i < 4; i++) {
        const int c   = tid + i * 256;
        const int row = c >> 3;
        const int c4  = c & 7;
        cp16(a0 + (uint32_t)(row * LDS_STRIDE + c4 * 4) * 4u,
             g_Hbuf + (size_t)(bm + row) * K_ + k0 + c4 * 4);
    }
    // B: 128 n-rows x 8 chunks = 1024 chunks; 4 per thread
#pragma unroll
    for (int i = 0; i < 4; i++) {
        const int c   = tid + i * 256;
        const int row = c >> 3;
        const int c4  = c & 7;
        cp16(b0 + (uint32_t)(row * LDS_STRIDE + c4 * 4) * 4u,
             g_Wt + (size_t)(bn + row) * K_ + k0 + c4 * 4);
    }
    CP_COMMIT();
}

__global__ void __launch_bounds__(256, 2) gemm_mma(float* __restrict__ C) {
    extern __shared__ float sm[];
    const uint32_t sbase = smem_u32(sm);
    const int tid  = threadIdx.x;
    const int lane = tid & 31;
    const int wid  = tid >> 5;
    const int wm   = (wid & 1) * 64;       // warp row offset (2 warps in M)
    const int wn   = (wid >> 1) * 32;      // warp col offset (4 warps in N)
    const int gr   = lane >> 2;            // group row (0..7)
    const int qc   = (lane & 3) * 2;       // interleaved pair column
    const int bm   = blockIdx.y * BM;
    const int bn   = blockIdx.x * BN;

    float acc[4][4][4];
#pragma unroll
    for (int mt = 0; mt < 4; mt++)
#pragma unroll
        for (int nt = 0; nt < 4; nt++)
#pragma unroll
            for (int i = 0; i < 4; i++) acc[mt][nt][i] = 0.f;

    fill_stage(sbase, 0, 0, bm, bn, tid);
    fill_stage(sbase, 1, 1, bm, bn, tid);

    int stage = 0;
    for (int kt = 0; kt < NT; kt++) {
        CP_WAIT(1);
        __syncthreads();

        if (kt + 2 < NT) {
            int ns = stage + 2; if (ns >= NSTAGE) ns -= NSTAGE;
            fill_stage(sbase, ns, kt + 2, bm, bn, tid);
        }

        const float* As = sm + stage * STAGE_F;
        const float* Bs = As + BM * LDS_STRIDE;

#pragma unroll
        for (int ks = 0; ks < 4; ks++) {        // 4 x k8 per BK
            uint32_t a[4][4];
#pragma unroll
            for (int mt = 0; mt < 4; mt++) {
                const int row = wm + mt * 16 + gr;
                const float2 lo = *(const float2*)(As + row * LDS_STRIDE + ks * 8 + qc);
                const float2 hi = *(const float2*)(As + (row + 8) * LDS_STRIDE + ks * 8 + qc);
                a[mt][0] = __float_as_uint(lo.x);
                a[mt][1] = __float_as_uint(hi.x);
                a[mt][2] = __float_as_uint(lo.y);
                a[mt][3] = __float_as_uint(hi.y);
            }
            uint32_t b[4][2];
#pragma unroll
            for (int nt = 0; nt < 4; nt++) {
                const int n = wn + nt * 8 + gr;
                const float2 bb = *(const float2*)(Bs + n * LDS_STRIDE + ks * 8 + qc);
                b[nt][0] = __float_as_uint(bb.x);
                b[nt][1] = __float_as_uint(bb.y);
            }
#pragma unroll
            for (int mt = 0; mt < 4; mt++)
#pragma unroll
                for (int nt = 0; nt < 4; nt++)
                    mma_tf32(acc[mt][nt], a[mt], b[nt]);
        }

        stage++; if (stage >= NSTAGE) stage = 0;
        __syncthreads();
    }

    // Epilogue: bias + store. Thread owns (gr, gr+8) x (qc, qc+1) per tile.
#pragma unroll
    for (int nt = 0; nt < 4; nt++) {
        const int col = bn + wn + nt * 8 + qc;
        const float2 bias = *(const float2*)&g_bias[col];
#pragma unroll
        for (int mt = 0; mt < 4; mt++) {
            const int row = bm + wm + mt * 16 + gr;
            float2 v0, v1;
            v0.x = acc[mt][nt][0] + bias.x;
            v0.y = acc[mt][nt][1] + bias.y;
            v1.x = acc[mt][nt][2] + bias.x;
            v1.y = acc[mt][nt][3] + bias.y;
            *(float2*)&C[(size_t)row * P_ + col]       = v0;
            *(float2*)&C[(size_t)(row + 8) * P_ + col] = v1;
        }
    }
}

// ---------------------------------------------------------------------------
// Launch: x, time, w1v, b1v, w2v, w1t, b1t, w2t, wx, bx, wt, bt
// ---------------------------------------------------------------------------
extern "C" void kernel_launch(void* const* d_in, const int* in_sizes, int n_in,
                              void* d_out, int out_size) {
    const float* x    = (const float*)d_in[0];
    const float* tmi  = (const float*)d_in[1];
    const float* w1v  = (const float*)d_in[2];
    const float* b1v  = (const float*)d_in[3];
    const float* w2v  = (const float*)d_in[4];
    const float* w1t  = (const float*)d_in[5];
    const float* b1t  = (const float*)d_in[6];
    const float* w2t  = (const float*)d_in[7];
    const float* wx   = (const float*)d_in[8];
    const float* bx   = (const float*)d_in[9];
    const float* wt   = (const float*)d_in[10];
    const float* bt   = (const float*)d_in[11];
    float* out = (float*)d_out;

    static bool attr_set = false;
    if (!attr_set) {
        cudaFuncSetAttribute(gemm_mma, cudaFuncAttributeMaxDynamicSharedMemorySize, SMEM_BYTES);
        attr_set = true;
    }

    precompute_W<<<dim3(F_, 2), P_>>>(w2v, wx, w2t, wt, bx, bt);
    tanh_act<<<(BT_ * K_) / 256, 256>>>(x, tmi, w1v, b1v, w1t, b1t);
    gemm_mma<<<dim3(P_ / BN, BT_ / BM), 256, SMEM_BYTES>>>(out);
}

// round 4
// speedup vs baseline: 5.1654x; 2.2071x over previous
#include <cuda_runtime.h>
#include <cuda_fp16.h>
#include <math.h>
#include <stdint.h>

// Problem constants
#define BT_  16384   // B*T
#define F_   64
#define E_   64
#define H_   8
#define P_   512
#define K_   1024    // 2*F*H

// GEMM tiling
#define BM 128
#define BN 128
#define BK 32
#define NT (K_ / BK)       // 32 k-tiles
#define NSTAGE 3
#define ROW_H   40                            // halves per smem row (32 + 8 pad, 80B: 16B-aligned, conflict-free ldmatrix)
#define STAGE_B ((BM + BN) * ROW_H * 2)       // bytes per stage = 20480
#define SMEM_BYTES (NSTAGE * STAGE_B)         // 61440

// Scratch (static device globals), plain row-major fp16
__device__ __half g_Wt[P_ * K_];      // folded weights [P][K] (1MB)
__device__ __half g_Hbuf[BT_ * K_];   // tanh activations [BT][K] (32MB)
__device__ float  g_bias[P_];

// ---------------------------------------------------------------------------
// helpers
// ---------------------------------------------------------------------------
__device__ __forceinline__ uint32_t smem_u32(const void* p) {
    uint32_t a;
    asm("{ .reg .u64 t; cvta.to.shared.u64 t, %1; cvt.u32.u64 %0, t; }" : "=r"(a) : "l"(p));
    return a;
}

__device__ __forceinline__ void cp16(uint32_t dst, const void* src) {
    asm volatile("cp.async.cg.shared.global [%0], [%1], 16;" :: "r"(dst), "l"(src) : "memory");
}

#define CP_COMMIT()  asm volatile("cp.async.commit_group;" ::: "memory")
#define CP_WAIT(n)   asm volatile("cp.async.wait_group %0;" :: "n"(n) : "memory")

__device__ __forceinline__ void ldmx4(uint32_t r[4], uint32_t addr) {
    asm volatile("ldmatrix.sync.aligned.m8n8.x4.shared.b16 {%0,%1,%2,%3}, [%4];"
                 : "=r"(r[0]), "=r"(r[1]), "=r"(r[2]), "=r"(r[3]) : "r"(addr));
}

__device__ __forceinline__ void mma_f16(float c[4], const uint32_t a[4], const uint32_t b0, const uint32_t b1) {
    asm volatile(
        "mma.sync.aligned.m16n8k16.row.col.f32.f16.f16.f32 "
        "{%0,%1,%2,%3}, {%4,%5,%6,%7}, {%8,%9}, {%0,%1,%2,%3};"
        : "+f"(c[0]), "+f"(c[1]), "+f"(c[2]), "+f"(c[3])
        : "r"(a[0]), "r"(a[1]), "r"(a[2]), "r"(a[3]), "r"(b0), "r"(b1));
}

// ---------------------------------------------------------------------------
// Kernel 1: fold E into weights; write TRANSPOSED fp16 g_Wt[p][k]
// grid (F, 2), block 512
// ---------------------------------------------------------------------------
__global__ void precompute_W(const float* __restrict__ w2v, const float* __restrict__ wx,
                             const float* __restrict__ w2t, const float* __restrict__ wt,
                             const float* __restrict__ bx,  const float* __restrict__ bt) {
    const int f      = blockIdx.x;
    const int branch = blockIdx.y;
    const int p      = threadIdx.x;

    const float* __restrict__ w2 = branch ? w2t : w2v;
    const float* __restrict__ wp = branch ? wt  : wx;

    __shared__ float s_w2[H_ * E_];
    if (p < H_ * E_) s_w2[p] = w2[f * H_ * E_ + p];
    __syncthreads();

    float acc[H_];
#pragma unroll
    for (int h = 0; h < H_; h++) acc[h] = 0.f;

#pragma unroll 16
    for (int e = 0; e < E_; e++) {
        const float w = wp[(size_t)(f * E_ + e) * P_ + p];
#pragma unroll
        for (int h = 0; h < H_; h++) acc[h] = fmaf(s_w2[h * E_ + e], w, acc[h]);
    }
    __half hh[8];
#pragma unroll
    for (int h = 0; h < H_; h++) hh[h] = __float2half_rn(acc[h]);
    *(uint4*)&g_Wt[(size_t)p * K_ + branch * 512 + f * H_] = *(uint4*)hh;

    if (f == 0 && branch == 0) g_bias[p] = bx[p] + bt[p];
}

// ---------------------------------------------------------------------------
// Kernel 2: tanh activations -> g_Hbuf [BT][K] fp16
// One thread per (bt, branch, f): computes 8 h values, 16B store.
// ---------------------------------------------------------------------------
__global__ void tanh_act(const float* __restrict__ x,   const float* __restrict__ tm,
                         const float* __restrict__ w1v, const float* __restrict__ b1v,
                         const float* __restrict__ w1t, const float* __restrict__ b1t) {
    const int idx    = blockIdx.x * blockDim.x + threadIdx.x;  // [0, BT*2*F)
    const int bt     = idx >> 7;         // / 128
    const int r      = idx & 127;
    const int branch = r >> 6;
    const int f      = r & 63;

    const float inp = (branch ? tm : x)[bt * F_ + f];
    const float4 w0 = *(const float4*)&(branch ? w1t : w1v)[f * H_];
    const float4 w1 = *(const float4*)&(branch ? w1t : w1v)[f * H_ + 4];
    const float4 b0 = *(const float4*)&(branch ? b1t : b1v)[f * H_];
    const float4 b1 = *(const float4*)&(branch ? b1t : b1v)[f * H_ + 4];

    __half hh[8];
    hh[0] = __float2half_rn(tanhf(fmaf(inp, w0.x, b0.x)));
    hh[1] = __float2half_rn(tanhf(fmaf(inp, w0.y, b0.y)));
    hh[2] = __float2half_rn(tanhf(fmaf(inp, w0.z, b0.z)));
    hh[3] = __float2half_rn(tanhf(fmaf(inp, w0.w, b0.w)));
    hh[4] = __float2half_rn(tanhf(fmaf(inp, w1.x, b1.x)));
    hh[5] = __float2half_rn(tanhf(fmaf(inp, w1.y, b1.y)));
    hh[6] = __float2half_rn(tanhf(fmaf(inp, w1.z, b1.z)));
    hh[7] = __float2half_rn(tanhf(fmaf(inp, w1.w, b1.w)));
    *(uint4*)&g_Hbuf[(size_t)bt * K_ + branch * 512 + f * H_] = *(uint4*)hh;
}

// ---------------------------------------------------------------------------
// Kernel 3: C[16384,512] = Hbuf @ Wt^T + bias, fp16 mma.sync m16n8k16
// grid (P/BN=4, BT/BM=128), 256 threads (8 warps: 2m x 4n), warp tile 64x32
// ---------------------------------------------------------------------------
__device__ __forceinline__ void fill_stage(uint32_t sbase, int stage, int kt, int bm, int bn, int tid) {
    const uint32_t a0 = sbase + (uint32_t)(stage * STAGE_B);
    const uint32_t b0 = a0 + (uint32_t)(BM * ROW_H * 2);
    const int k0 = kt * BK;
    // A: 128 rows x 4 chunks of 16B = 512 chunks; 2 per thread
#pragma unroll
    for (int i = 0; i < 2; i++) {
        const int c   = tid + i * 256;
        const int row = c >> 2;
        const int ch  = c & 3;
        cp16(a0 + (uint32_t)(row * ROW_H * 2 + ch * 16),
             g_Hbuf + (size_t)(bm + row) * K_ + k0 + ch * 8);
    }
    // B: 128 n-rows x 4 chunks = 512 chunks; 2 per thread
#pragma unroll
    for (int i = 0; i < 2; i++) {
        const int c   = tid + i * 256;
        const int row = c >> 2;
        const int ch  = c & 3;
        cp16(b0 + (uint32_t)(row * ROW_H * 2 + ch * 16),
             g_Wt + (size_t)(bn + row) * K_ + k0 + ch * 8);
    }
    CP_COMMIT();
}

__global__ void __launch_bounds__(256, 2) gemm_mma(float* __restrict__ C) {
    extern __shared__ char sm[];
    const uint32_t sbase = smem_u32(sm);
    const int tid  = threadIdx.x;
    const int lane = tid & 31;
    const int wid  = tid >> 5;
    const int wm   = (wid & 1) * 64;       // warp row offset (2 warps in M)
    const int wn   = (wid >> 1) * 32;      // warp col offset (4 warps in N)
    const int bm   = blockIdx.y * BM;
    const int bn   = blockIdx.x * BN;

    // ldmatrix lane-address components (bytes within tile)
    // A x4 (16x16): lanes 0-7: rows 0-7,k0 | 8-15: rows 8-15,k0 | 16-23: rows 0-7,k8 | 24-31: rows 8-15,k8
    const uint32_t a_lane = (uint32_t)((wm + (lane & 15)) * ROW_H * 2 + ((lane >> 4) & 1) * 16);
    // B x4 (n16 x k16): lanes 0-7: n0-7,k0 | 8-15: n0-7,k8 | 16-23: n8-15,k0 | 24-31: n8-15,k8
    const uint32_t b_lane = (uint32_t)((wn + (lane & 7) + ((lane >> 4) & 1) * 8) * ROW_H * 2
                                       + ((lane >> 3) & 1) * 16);

    float acc[4][4][4];
#pragma unroll
    for (int mt = 0; mt < 4; mt++)
#pragma unroll
        for (int nt = 0; nt < 4; nt++)
#pragma unroll
            for (int i = 0; i < 4; i++) acc[mt][nt][i] = 0.f;

    fill_stage(sbase, 0, 0, bm, bn, tid);
    fill_stage(sbase, 1, 1, bm, bn, tid);

    int stage = 0;
    for (int kt = 0; kt < NT; kt++) {
        CP_WAIT(1);
        __syncthreads();

        if (kt + 2 < NT) {
            int ns = stage + 2; if (ns >= NSTAGE) ns -= NSTAGE;
            fill_stage(sbase, ns, kt + 2, bm, bn, tid);
        }

        const uint32_t Abase = sbase + (uint32_t)(stage * STAGE_B);
        const uint32_t Bbase = Abase + (uint32_t)(BM * ROW_H * 2);

#pragma unroll
        for (int ks = 0; ks < 2; ks++) {        // 2 x k16 per BK
            // B fragments: 2 x ldmatrix.x4, each covers 2 n-tiles
            uint32_t b[4][2];
#pragma unroll
            for (int np = 0; np < 2; np++) {
                uint32_t r[4];
                ldmx4(r, Bbase + b_lane + (uint32_t)(np * 16 * ROW_H * 2 + ks * 32));
                b[np * 2 + 0][0] = r[0]; b[np * 2 + 0][1] = r[1];
                b[np * 2 + 1][0] = r[2]; b[np * 2 + 1][1] = r[3];
            }
#pragma unroll
            for (int mt = 0; mt < 4; mt++) {
                uint32_t a[4];
                ldmx4(a, Abase + a_lane + (uint32_t)(mt * 16 * ROW_H * 2 + ks * 32));
#pragma unroll
                for (int nt = 0; nt < 4; nt++)
                    mma_f16(acc[mt][nt], a, b[nt][0], b[nt][1]);
            }
        }

        stage++; if (stage >= NSTAGE) stage = 0;
        __syncthreads();
    }

    // Epilogue: thread owns rows {g, g+8}, cols {qc, qc+1} per (mt, nt) tile
    const int g  = lane >> 2;
    const int qc = (lane & 3) * 2;
#pragma unroll
    for (int nt = 0; nt < 4; nt++) {
        const int col = bn + wn + nt * 8 + qc;
        const float2 bias = *(const float2*)&g_bias[col];
#pragma unroll
        for (int mt = 0; mt < 4; mt++) {
            const int row = bm + wm + mt * 16 + g;
            float2 v0, v1;
            v0.x = acc[mt][nt][0] + bias.x;
            v0.y = acc[mt][nt][1] + bias.y;
            v1.x = acc[mt][nt][2] + bias.x;
            v1.y = acc[mt][nt][3] + bias.y;
            *(float2*)&C[(size_t)row * P_ + col]       = v0;
            *(float2*)&C[(size_t)(row + 8) * P_ + col] = v1;
        }
    }
}

// ---------------------------------------------------------------------------
// Launch: x, time, w1v, b1v, w2v, w1t, b1t, w2t, wx, bx, wt, bt
// ---------------------------------------------------------------------------
extern "C" void kernel_launch(void* const* d_in, const int* in_sizes, int n_in,
                              void* d_out, int out_size) {
    const float* x    = (const float*)d_in[0];
    const float* tmi  = (const float*)d_in[1];
    const float* w1v  = (const float*)d_in[2];
    const float* b1v  = (const float*)d_in[3];
    const float* w2v  = (const float*)d_in[4];
    const float* w1t  = (const float*)d_in[5];
    const float* b1t  = (const float*)d_in[6];
    const float* w2t  = (const float*)d_in[7];
    const float* wx   = (const float*)d_in[8];
    const float* bx   = (const float*)d_in[9];
    const float* wt   = (const float*)d_in[10];
    const float* bt   = (const float*)d_in[11];
    float* out = (float*)d_out;

    static bool attr_set = false;
    if (!attr_set) {
        cudaFuncSetAttribute(gemm_mma, cudaFuncAttributeMaxDynamicSharedMemorySize, SMEM_BYTES);
        attr_set = true;
    }

    precompute_W<<<dim3(F_, 2), P_>>>(w2v, wx, w2t, wt, bx, bt);
    tanh_act<<<(BT_ * 2 * F_) / 256, 256>>>(x, tmi, w1v, b1v, w1t, b1t);
    gemm_mma<<<dim3(P_ / BN, BT_ / BM), 256, SMEM_BYTES>>>(out);
}

// round 5
// speedup vs baseline: 5.6854x; 1.1007x over previous
#include <cuda_runtime.h>
#include <cuda_fp16.h>
#include <math.h>
#include <stdint.h>

// Problem constants
#define BT_  16384   // B*T
#define F_   64
#define E_   64
#define H_   8
#define P_   512
#define K_   1024    // 2*F*H

// GEMM tiling
#define BM 128
#define BN 128
#define BK 64
#define NT (K_ / BK)       // 16 k-tiles
#define NSTAGE 3
#define ROWB 144                         // bytes per smem row (128 + 16 pad; granule stride 9 -> conflict-free ldmatrix)
#define STAGE_B ((BM + BN) * ROWB)       // 36864 bytes per stage
#define SMEM_BYTES (NSTAGE * STAGE_B)    // 110592

// Scratch (static device globals), plain row-major fp16
__device__ __half g_Wt[P_ * K_];      // folded weights [P][K] (1MB)
__device__ __half g_Hbuf[BT_ * K_];   // tanh activations [BT][K] (32MB)
__device__ float  g_bias[P_];

// ---------------------------------------------------------------------------
// helpers
// ---------------------------------------------------------------------------
__device__ __forceinline__ uint32_t smem_u32(const void* p) {
    uint32_t a;
    asm("{ .reg .u64 t; cvta.to.shared.u64 t, %1; cvt.u32.u64 %0, t; }" : "=r"(a) : "l"(p));
    return a;
}

__device__ __forceinline__ void cp16(uint32_t dst, const void* src) {
    asm volatile("cp.async.cg.shared.global [%0], [%1], 16;" :: "r"(dst), "l"(src) : "memory");
}

#define CP_COMMIT()  asm volatile("cp.async.commit_group;" ::: "memory")
#define CP_WAIT(n)   asm volatile("cp.async.wait_group %0;" :: "n"(n) : "memory")

__device__ __forceinline__ void ldmx4(uint32_t r[4], uint32_t addr) {
    asm volatile("ldmatrix.sync.aligned.m8n8.x4.shared.b16 {%0,%1,%2,%3}, [%4];"
                 : "=r"(r[0]), "=r"(r[1]), "=r"(r[2]), "=r"(r[3]) : "r"(addr));
}

__device__ __forceinline__ void mma_f16(float c[4], const uint32_t a[4], const uint32_t b0, const uint32_t b1) {
    asm volatile(
        "mma.sync.aligned.m16n8k16.row.col.f32.f16.f16.f32 "
        "{%0,%1,%2,%3}, {%4,%5,%6,%7}, {%8,%9}, {%0,%1,%2,%3};"
        : "+f"(c[0]), "+f"(c[1]), "+f"(c[2]), "+f"(c[3])
        : "r"(a[0]), "r"(a[1]), "r"(a[2]), "r"(a[3]), "r"(b0), "r"(b1));
}

// ---------------------------------------------------------------------------
// Kernel 1: fold E into weights; write TRANSPOSED fp16 g_Wt[p][k]
// grid (F, 2, 4), block 128: each block covers 128 p values
// ---------------------------------------------------------------------------
__global__ void precompute_W(const float* __restrict__ w2v, const float* __restrict__ wx,
                             const float* __restrict__ w2t, const float* __restrict__ wt,
                             const float* __restrict__ bx,  const float* __restrict__ bt) {
    const int f      = blockIdx.x;
    const int branch = blockIdx.y;
    const int p      = blockIdx.z * 128 + threadIdx.x;

    const float* __restrict__ w2 = branch ? w2t : w2v;
    const float* __restrict__ wp = branch ? wt  : wx;

    __shared__ float s_w2[H_ * E_];
#pragma unroll
    for (int i = 0; i < 4; i++)
        s_w2[threadIdx.x + i * 128] = w2[f * H_ * E_ + threadIdx.x + i * 128];
    __syncthreads();

    float acc[H_];
#pragma unroll
    for (int h = 0; h < H_; h++) acc[h] = 0.f;

#pragma unroll 16
    for (int e = 0; e < E_; e++) {
        const float w = wp[(size_t)(f * E_ + e) * P_ + p];
#pragma unroll
        for (int h = 0; h < H_; h++) acc[h] = fmaf(s_w2[h * E_ + e], w, acc[h]);
    }
    __half hh[8];
#pragma unroll
    for (int h = 0; h < H_; h++) hh[h] = __float2half_rn(acc[h]);
    *(uint4*)&g_Wt[(size_t)p * K_ + branch * 512 + f * H_] = *(uint4*)hh;

    if (f == 0 && branch == 0 && blockIdx.z == 0) {
        const int q = threadIdx.x;
#pragma unroll
        for (int i = 0; i < 4; i++) g_bias[q + i * 128] = bx[q + i * 128] + bt[q + i * 128];
    }
}

// ---------------------------------------------------------------------------
// Kernel 2: tanh activations -> g_Hbuf [BT][K] fp16
// ---------------------------------------------------------------------------
__global__ void tanh_act(const float* __restrict__ x,   const float* __restrict__ tm,
                         const float* __restrict__ w1v, const float* __restrict__ b1v,
                         const float* __restrict__ w1t, const float* __restrict__ b1t) {
    const int idx    = blockIdx.x * blockDim.x + threadIdx.x;  // [0, BT*2*F)
    const int bt     = idx >> 7;
    const int r      = idx & 127;
    const int branch = r >> 6;
    const int f      = r & 63;

    const float inp = (branch ? tm : x)[bt * F_ + f];
    const float4 w0 = *(const float4*)&(branch ? w1t : w1v)[f * H_];
    const float4 w1 = *(const float4*)&(branch ? w1t : w1v)[f * H_ + 4];
    const float4 b0 = *(const float4*)&(branch ? b1t : b1v)[f * H_];
    const float4 b1 = *(const float4*)&(branch ? b1t : b1v)[f * H_ + 4];

    __half hh[8];
    hh[0] = __float2half_rn(tanhf(fmaf(inp, w0.x, b0.x)));
    hh[1] = __float2half_rn(tanhf(fmaf(inp, w0.y, b0.y)));
    hh[2] = __float2half_rn(tanhf(fmaf(inp, w0.z, b0.z)));
    hh[3] = __float2half_rn(tanhf(fmaf(inp, w0.w, b0.w)));
    hh[4] = __float2half_rn(tanhf(fmaf(inp, w1.x, b1.x)));
    hh[5] = __float2half_rn(tanhf(fmaf(inp, w1.y, b1.y)));
    hh[6] = __float2half_rn(tanhf(fmaf(inp, w1.z, b1.z)));
    hh[7] = __float2half_rn(tanhf(fmaf(inp, w1.w, b1.w)));
    *(uint4*)&g_Hbuf[(size_t)bt * K_ + branch * 512 + f * H_] = *(uint4*)hh;
}

// ---------------------------------------------------------------------------
// Kernel 3: C[16384,512] = Hbuf @ Wt^T + bias, fp16 mma.sync m16n8k16
// grid (P/BN=4, BT/BM=128), 256 threads (8 warps: 2m x 4n), warp tile 64x32
// ---------------------------------------------------------------------------
__device__ __forceinline__ void fill_stage(uint32_t sbase, int stage, int kt, int bm, int bn, int tid) {
    const uint32_t a0 = sbase + (uint32_t)(stage * STAGE_B);
    const uint32_t b0 = a0 + (uint32_t)(BM * ROWB);
    const int k0 = kt * BK;
    // A: 128 rows x 8 chunks of 16B = 1024 chunks; 4 per thread
#pragma unroll
    for (int i = 0; i < 4; i++) {
        const int c   = tid + i * 256;
        const int row = c >> 3;
        const int ch  = c & 7;
        cp16(a0 + (uint32_t)(row * ROWB + ch * 16),
             g_Hbuf + (size_t)(bm + row) * K_ + k0 + ch * 8);
    }
    // B: 128 n-rows x 8 chunks = 1024 chunks; 4 per thread
#pragma unroll
    for (int i = 0; i < 4; i++) {
        const int c   = tid + i * 256;
        const int row = c >> 3;
        const int ch  = c & 7;
        cp16(b0 + (uint32_t)(row * ROWB + ch * 16),
             g_Wt + (size_t)(bn + row) * K_ + k0 + ch * 8);
    }
}

__global__ void __launch_bounds__(256, 2) gemm_mma(float* __restrict__ C) {
    extern __shared__ char sm[];
    const uint32_t sbase = smem_u32(sm);
    const int tid  = threadIdx.x;
    const int lane = tid & 31;
    const int wid  = tid >> 5;
    const int wm   = (wid & 1) * 64;       // 2 warps in M
    const int wn   = (wid >> 1) * 32;      // 4 warps in N
    const int bm   = blockIdx.y * BM;
    const int bn   = blockIdx.x * BN;

    // ldmatrix lane addresses (bytes within tile)
    const uint32_t a_lane = (uint32_t)((wm + (lane & 15)) * ROWB + ((lane >> 4) & 1) * 16);
    const uint32_t b_lane = (uint32_t)((wn + (lane & 7) + ((lane >> 4) & 1) * 8) * ROWB
                                       + ((lane >> 3) & 1) * 16);

    float acc[4][4][4];
#pragma unroll
    for (int mt = 0; mt < 4; mt++)
#pragma unroll
        for (int nt = 0; nt < 4; nt++)
#pragma unroll
            for (int i = 0; i < 4; i++) acc[mt][nt][i] = 0.f;

    fill_stage(sbase, 0, 0, bm, bn, tid); CP_COMMIT();
    fill_stage(sbase, 1, 1, bm, bn, tid); CP_COMMIT();

    int stage = 0;
    for (int kt = 0; kt < NT; kt++) {
        CP_WAIT(1);             // stage kt resident (one commit per iter keeps this exact)
        __syncthreads();

        // one commit per iteration (empty group at tail) keeps wait_group arithmetic valid
        if (kt + 2 < NT) {
            int ns = stage + 2; if (ns >= NSTAGE) ns -= NSTAGE;
            fill_stage(sbase, ns, kt + 2, bm, bn, tid);
        }
        CP_COMMIT();

        const uint32_t Abase = sbase + (uint32_t)(stage * STAGE_B);
        const uint32_t Bbase = Abase + (uint32_t)(BM * ROWB);

        uint32_t a[2][4];       // double-buffered A fragment (per mt)
        uint32_t b[2][8];       // double-buffered B fragments (per ks: 4 nt x 2 regs)

        // preload ks=0
        {
            uint32_t r[4];
            ldmx4(r, Bbase + b_lane);                         // np=0 -> nt 0,1
            b[0][0] = r[0]; b[0][1] = r[1]; b[0][2] = r[2]; b[0][3] = r[3];
            ldmx4(r, Bbase + b_lane + 16u * ROWB);            // np=1 -> nt 2,3
            b[0][4] = r[0]; b[0][5] = r[1]; b[0][6] = r[2]; b[0][7] = r[3];
            ldmx4(a[0], Abase + a_lane);                      // mt=0, ks=0
        }

#pragma unroll
        for (int ks = 0; ks < 4; ks++) {
            const uint32_t* bc = b[ks & 1];
            if (ks < 3) {       // prefetch B for ks+1
                uint32_t* bn_ = b[(ks + 1) & 1];
                uint32_t r[4];
                ldmx4(r, Bbase + b_lane + (uint32_t)((ks + 1) * 32));
                bn_[0] = r[0]; bn_[1] = r[1]; bn_[2] = r[2]; bn_[3] = r[3];
                ldmx4(r, Bbase + b_lane + (uint32_t)(16 * ROWB + (ks + 1) * 32));
                bn_[4] = r[0]; bn_[5] = r[1]; bn_[6] = r[2]; bn_[7] = r[3];
            }
#pragma unroll
            for (int mt = 0; mt < 4; mt++) {
                if (mt < 3)
                    ldmx4(a[(mt + 1) & 1], Abase + a_lane + (uint32_t)((mt + 1) * 16 * ROWB + ks * 32));
                else if (ks < 3)
                    ldmx4(a[0], Abase + a_lane + (uint32_t)((ks + 1) * 32));
                const uint32_t* ac = a[mt & 1];
#pragma unroll
                for (int nt = 0; nt < 4; nt++)
                    mma_f16(acc[mt][nt], ac, bc[nt * 2], bc[nt * 2 + 1]);
            }
        }

        stage++; if (stage >= NSTAGE) stage = 0;
    }

    // Epilogue: thread owns rows {g, g+8}, cols {qc, qc+1} per (mt, nt) tile
    const int g  = lane >> 2;
    const int qc = (lane & 3) * 2;
#pragma unroll
    for (int nt = 0; nt < 4; nt++) {
        const int col = bn + wn + nt * 8 + qc;
        const float2 bias = *(const float2*)&g_bias[col];
#pragma unroll
        for (int mt = 0; mt < 4; mt++) {
            const int row = bm + wm + mt * 16 + g;
            float2 v0, v1;
            v0.x = acc[mt][nt][0] + bias.x;
            v0.y = acc[mt][nt][1] + bias.y;
            v1.x = acc[mt][nt][2] + bias.x;
            v1.y = acc[mt][nt][3] + bias.y;
            *(float2*)&C[(size_t)row * P_ + col]       = v0;
            *(float2*)&C[(size_t)(row + 8) * P_ + col] = v1;
        }
    }
}

// ---------------------------------------------------------------------------
// Launch: x, time, w1v, b1v, w2v, w1t, b1t, w2t, wx, bx, wt, bt
// ---------------------------------------------------------------------------
extern "C" void kernel_launch(void* const* d_in, const int* in_sizes, int n_in,
                              void* d_out, int out_size) {
    const float* x    = (const float*)d_in[0];
    const float* tmi  = (const float*)d_in[1];
    const float* w1v  = (const float*)d_in[2];
    const float* b1v  = (const float*)d_in[3];
    const float* w2v  = (const float*)d_in[4];
    const float* w1t  = (const float*)d_in[5];
    const float* b1t  = (const float*)d_in[6];
    const float* w2t  = (const float*)d_in[7];
    const float* wx   = (const float*)d_in[8];
    const float* bx   = (const float*)d_in[9];
    const float* wt   = (const float*)d_in[10];
    const float* bt   = (const float*)d_in[11];
    float* out = (float*)d_out;

    static bool attr_set = false;
    if (!attr_set) {
        cudaFuncSetAttribute(gemm_mma, cudaFuncAttributeMaxDynamicSharedMemorySize, SMEM_BYTES);
        attr_set = true;
    }

    precompute_W<<<dim3(F_, 2, 4), 128>>>(w2v, wx, w2t, wt, bx, bt);
    tanh_act<<<(BT_ * 2 * F_) / 256, 256>>>(x, tmi, w1v, b1v, w1t, b1t);
    gemm_mma<<<dim3(P_ / BN, BT_ / BM), 256, SMEM_BYTES>>>(out);
}

// round 6
// speedup vs baseline: 5.7970x; 1.0196x over previous
#include <cuda_runtime.h>
#include <cuda_fp16.h>
#include <math.h>
#include <stdint.h>

// Problem constants
#define BT_  16384   // B*T
#define F_   64
#define E_   64
#define H_   8
#define P_   512
#define K_   1024    // 2*F*H

// GEMM tiling
#define BM 128
#define BN 256
#define BK 64
#define NT (K_ / BK)       // 16 k-tiles
#define NSTAGE 4
#define ROWB 144                         // 128B payload + 16B pad (stride 9 granules -> conflict-free ldmatrix)
#define A_BYTES (BM * ROWB)              // 18432
#define STAGE_B ((BM + BN) * ROWB)       // 55296
#define SMEM_BYTES (NSTAGE * STAGE_B)    // 221184

// Scratch (static device globals), plain row-major fp16
__device__ __half g_Wt[P_ * K_];      // folded weights [P][K] (1MB)
__device__ __half g_Hbuf[BT_ * K_];   // tanh activations [BT][K] (32MB)
__device__ float  g_bias[P_];

// ---------------------------------------------------------------------------
// helpers
// ---------------------------------------------------------------------------
__device__ __forceinline__ uint32_t smem_u32(const void* p) {
    uint32_t a;
    asm("{ .reg .u64 t; cvta.to.shared.u64 t, %1; cvt.u32.u64 %0, t; }" : "=r"(a) : "l"(p));
    return a;
}

__device__ __forceinline__ void cp16(uint32_t dst, const void* src) {
    asm volatile("cp.async.cg.shared.global [%0], [%1], 16;" :: "r"(dst), "l"(src) : "memory");
}

#define CP_COMMIT()  asm volatile("cp.async.commit_group;" ::: "memory")
#define CP_WAIT(n)   asm volatile("cp.async.wait_group %0;" :: "n"(n) : "memory")

__device__ __forceinline__ void ldmx4(uint32_t r[4], uint32_t addr) {
    asm volatile("ldmatrix.sync.aligned.m8n8.x4.shared.b16 {%0,%1,%2,%3}, [%4];"
                 : "=r"(r[0]), "=r"(r[1]), "=r"(r[2]), "=r"(r[3]) : "r"(addr));
}

__device__ __forceinline__ void mma_f16(float c[4], const uint32_t a[4], const uint32_t b0, const uint32_t b1) {
    asm volatile(
        "mma.sync.aligned.m16n8k16.row.col.f32.f16.f16.f32 "
        "{%0,%1,%2,%3}, {%4,%5,%6,%7}, {%8,%9}, {%0,%1,%2,%3};"
        : "+f"(c[0]), "+f"(c[1]), "+f"(c[2]), "+f"(c[3])
        : "r"(a[0]), "r"(a[1]), "r"(a[2]), "r"(a[3]), "r"(b0), "r"(b1));
}

__device__ __forceinline__ float tanh_fast(float x) {
    float r;
    asm("tanh.approx.f32 %0, %1;" : "=f"(r) : "f"(x));
    return r;
}

// ---------------------------------------------------------------------------
// Fused prep kernel (256 threads/block):
//   blocks [0, 128):  precompute_W — fold E into weights, write fp16 g_Wt[p][k]
//                     block = (f, branch) = (bid>>1, bid&1); thread covers p, p+256
//   blocks [128, 8320): tanh activations -> g_Hbuf fp16 (one thread per (bt,branch,f))
//   block 0 additionally writes g_bias.
// ---------------------------------------------------------------------------
__global__ void __launch_bounds__(256) prep(
        const float* __restrict__ x,   const float* __restrict__ tm,
        const float* __restrict__ w1v, const float* __restrict__ b1v,
        const float* __restrict__ w2v,
        const float* __restrict__ w1t, const float* __restrict__ b1t,
        const float* __restrict__ w2t,
        const float* __restrict__ wx,  const float* __restrict__ bx,
        const float* __restrict__ wt,  const float* __restrict__ bt) {
    const int bid = blockIdx.x;
    const int t   = threadIdx.x;

    if (bid < 128) {
        // ---- precompute_W part ----
        const int f      = bid >> 1;
        const int branch = bid & 1;
        const float* __restrict__ w2 = branch ? w2t : w2v;
        const float* __restrict__ wp = branch ? wt  : wx;

        __shared__ float s_w2[H_ * E_];
        s_w2[t]       = w2[f * H_ * E_ + t];
        s_w2[t + 256] = w2[f * H_ * E_ + t + 256];
        __syncthreads();

        float acc0[H_], acc1[H_];
#pragma unroll
        for (int h = 0; h < H_; h++) { acc0[h] = 0.f; acc1[h] = 0.f; }

#pragma unroll 8
        for (int e = 0; e < E_; e++) {
            const float* row = wp + (size_t)(f * E_ + e) * P_;
            const float wA = row[t];
            const float wB = row[t + 256];
#pragma unroll
            for (int h = 0; h < H_; h++) {
                const float s = s_w2[h * E_ + e];
                acc0[h] = fmaf(s, wA, acc0[h]);
                acc1[h] = fmaf(s, wB, acc1[h]);
            }
        }
        __half hh0[8], hh1[8];
#pragma unroll
        for (int h = 0; h < H_; h++) { hh0[h] = __float2half_rn(acc0[h]); hh1[h] = __float2half_rn(acc1[h]); }
        const size_t koff = branch * 512 + f * H_;
        *(uint4*)&g_Wt[(size_t)t * K_ + koff]         = *(uint4*)hh0;
        *(uint4*)&g_Wt[(size_t)(t + 256) * K_ + koff] = *(uint4*)hh1;

        if (bid == 0) {
            g_bias[t]       = bx[t]       + bt[t];
            g_bias[t + 256] = bx[t + 256] + bt[t + 256];
        }
    } else {
        // ---- tanh activation part ----
        const int idx    = (bid - 128) * 256 + t;   // [0, BT*128)
        const int bt_    = idx >> 7;
        const int r      = idx & 127;
        const int branch = r >> 6;
        const int f      = r & 63;

        const float inp = (branch ? tm : x)[bt_ * F_ + f];
        const float4 w0 = *(const float4*)&(branch ? w1t : w1v)[f * H_];
        const float4 w1 = *(const float4*)&(branch ? w1t : w1v)[f * H_ + 4];
        const float4 c0 = *(const float4*)&(branch ? b1t : b1v)[f * H_];
        const float4 c1 = *(const float4*)&(branch ? b1t : b1v)[f * H_ + 4];

        __half hh[8];
        hh[0] = __float2half_rn(tanh_fast(fmaf(inp, w0.x, c0.x)));
        hh[1] = __float2half_rn(tanh_fast(fmaf(inp, w0.y, c0.y)));
        hh[2] = __float2half_rn(tanh_fast(fmaf(inp, w0.z, c0.z)));
        hh[3] = __float2half_rn(tanh_fast(fmaf(inp, w0.w, c0.w)));
        hh[4] = __float2half_rn(tanh_fast(fmaf(inp, w1.x, c1.x)));
        hh[5] = __float2half_rn(tanh_fast(fmaf(inp, w1.y, c1.y)));
        hh[6] = __float2half_rn(tanh_fast(fmaf(inp, w1.z, c1.z)));
        hh[7] = __float2half_rn(tanh_fast(fmaf(inp, w1.w, c1.w)));
        *(uint4*)&g_Hbuf[(size_t)bt_ * K_ + branch * 512 + f * H_] = *(uint4*)hh;
    }
}

// ---------------------------------------------------------------------------
// GEMM: C[16384,512] = Hbuf @ Wt^T + bias, fp16 mma.sync m16n8k16
// CTA tile 128x256, 256 threads (8 warps: 2m x 4n), warp tile 64x64,
// 4-stage cp.async pipeline (221KB smem, occ 1)
// grid (512/BN=2, 16384/BM=128) = 256 CTAs
// ---------------------------------------------------------------------------
__device__ __forceinline__ void fill_stage(uint32_t sbase, int stage, int kt, int bm, int bn, int tid) {
    const uint32_t a0 = sbase + (uint32_t)(stage * STAGE_B);
    const uint32_t b0 = a0 + (uint32_t)A_BYTES;
    const int k0 = kt * BK;
    // A: 128 rows x 8 chunks of 16B = 1024 chunks; 4 per thread
#pragma unroll
    for (int i = 0; i < 4; i++) {
        const int c   = tid + i * 256;
        const int row = c >> 3;
        const int ch  = c & 7;
        cp16(a0 + (uint32_t)(row * ROWB + ch * 16),
             g_Hbuf + (size_t)(bm + row) * K_ + k0 + ch * 8);
    }
    // B: 256 n-rows x 8 chunks = 2048 chunks; 8 per thread
#pragma unroll
    for (int i = 0; i < 8; i++) {
        const int c   = tid + i * 256;
        const int row = c >> 3;
        const int ch  = c & 7;
        cp16(b0 + (uint32_t)(row * ROWB + ch * 16),
             g_Wt + (size_t)(bn + row) * K_ + k0 + ch * 8);
    }
}

__global__ void __launch_bounds__(256, 1) gemm_mma(float* __restrict__ C) {
    extern __shared__ char sm[];
    const uint32_t sbase = smem_u32(sm);
    const int tid  = threadIdx.x;
    const int lane = tid & 31;
    const int wid  = tid >> 5;
    const int wm   = (wid & 1) * 64;       // 2 warps in M
    const int wn   = (wid >> 1) * 64;      // 4 warps in N
    const int bm   = blockIdx.y * BM;
    const int bn   = blockIdx.x * BN;

    // ldmatrix lane addresses (bytes within tile)
    const uint32_t a_lane = (uint32_t)((wm + (lane & 15)) * ROWB + ((lane >> 4) & 1) * 16);
    const uint32_t b_lane = (uint32_t)((wn + (lane & 7) + ((lane >> 4) & 1) * 8) * ROWB
                                       + ((lane >> 3) & 1) * 16);

    float acc[4][8][4];
#pragma unroll
    for (int mt = 0; mt < 4; mt++)
#pragma unroll
        for (int nt = 0; nt < 8; nt++)
#pragma unroll
            for (int i = 0; i < 4; i++) acc[mt][nt][i] = 0.f;

    fill_stage(sbase, 0, 0, bm, bn, tid); CP_COMMIT();
    fill_stage(sbase, 1, 1, bm, bn, tid); CP_COMMIT();
    fill_stage(sbase, 2, 2, bm, bn, tid); CP_COMMIT();

    for (int kt = 0; kt < NT; kt++) {
        const int stage = kt & 3;
        CP_WAIT(2);
        __syncthreads();

        if (kt + 3 < NT)
            fill_stage(sbase, (kt + 3) & 3, kt + 3, bm, bn, tid);
        CP_COMMIT();    // one commit per iter keeps wait_group arithmetic exact

        const uint32_t Abase = sbase + (uint32_t)(stage * STAGE_B);
        const uint32_t Bbase = Abase + (uint32_t)A_BYTES;

        uint32_t a[2][4];    // A fragment, double-buffered per mt
        uint32_t b[2][16];   // B fragments per ks (8 n8-tiles x 2 regs), double-buffered

        // preload ks=0
#pragma unroll
        for (int np = 0; np < 4; np++)
            ldmx4(&b[0][np * 4], Bbase + b_lane + (uint32_t)(np * 16 * ROWB));
        ldmx4(a[0], Abase + a_lane);

#pragma unroll
        for (int ks = 0; ks < 4; ks++) {
            const uint32_t* bc = b[ks & 1];
            if (ks < 3) {    // prefetch B for ks+1
                uint32_t* bnx = b[(ks + 1) & 1];
#pragma unroll
                for (int np = 0; np < 4; np++)
                    ldmx4(&bnx[np * 4], Bbase + b_lane + (uint32_t)(np * 16 * ROWB + (ks + 1) * 32));
            }
#pragma unroll
            for (int mt = 0; mt < 4; mt++) {
                if (mt < 3)
                    ldmx4(a[(mt + 1) & 1], Abase + a_lane + (uint32_t)((mt + 1) * 16 * ROWB + ks * 32));
                else if (ks < 3)
                    ldmx4(a[0], Abase + a_lane + (uint32_t)((ks + 1) * 32));
                const uint32_t* ac = a[mt & 1];
#pragma unroll
                for (int nt = 0; nt < 8; nt++)
                    mma_f16(acc[mt][nt], ac, bc[nt * 2], bc[nt * 2 + 1]);
            }
        }
    }

    // Epilogue: thread owns rows {g, g+8}, cols {qc, qc+1} per (mt, nt) tile
    const int g  = lane >> 2;
    const int qc = (lane & 3) * 2;
#pragma unroll
    for (int nt = 0; nt < 8; nt++) {
        const int col = bn + wn + nt * 8 + qc;
        const float2 bias = *(const float2*)&g_bias[col];
#pragma unroll
        for (int mt = 0; mt < 4; mt++) {
            const int row = bm + wm + mt * 16 + g;
            float2 v0, v1;
            v0.x = acc[mt][nt][0] + bias.x;
            v0.y = acc[mt][nt][1] + bias.y;
            v1.x = acc[mt][nt][2] + bias.x;
            v1.y = acc[mt][nt][3] + bias.y;
            *(float2*)&C[(size_t)row * P_ + col]       = v0;
            *(float2*)&C[(size_t)(row + 8) * P_ + col] = v1;
        }
    }
}

// ---------------------------------------------------------------------------
// Launch: x, time, w1v, b1v, w2v, w1t, b1t, w2t, wx, bx, wt, bt
// ---------------------------------------------------------------------------
extern "C" void kernel_launch(void* const* d_in, const int* in_sizes, int n_in,
                              void* d_out, int out_size) {
    const float* x    = (const float*)d_in[0];
    const float* tmi  = (const float*)d_in[1];
    const float* w1v  = (const float*)d_in[2];
    const float* b1v  = (const float*)d_in[3];
    const float* w2v  = (const float*)d_in[4];
    const float* w1t  = (const float*)d_in[5];
    const float* b1t  = (const float*)d_in[6];
    const float* w2t  = (const float*)d_in[7];
    const float* wx   = (const float*)d_in[8];
    const float* bx   = (const float*)d_in[9];
    const float* wt   = (const float*)d_in[10];
    const float* bt   = (const float*)d_in[11];
    float* out = (float*)d_out;

    static bool attr_set = false;
    if (!attr_set) {
        cudaFuncSetAttribute(gemm_mma, cudaFuncAttributeMaxDynamicSharedMemorySize, SMEM_BYTES);
        attr_set = true;
    }

    prep<<<128 + (BT_ * 2 * F_) / 256, 256>>>(x, tmi, w1v, b1v, w2v, w1t, b1t, w2t, wx, bx, wt, bt);
    gemm_mma<<<dim3(P_ / BN, BT_ / BM), 256, SMEM_BYTES>>>(out);
}

// round 8
// speedup vs baseline: 5.8455x; 1.0084x over previous
#include <cuda_runtime.h>
#include <cuda_fp16.h>
#include <math.h>
#include <stdint.h>

// Problem constants
#define BT_  16384   // B*T
#define F_   64
#define E_   64
#define H_   8
#define P_   512
#define K_   1024    // 2*F*H

// GEMM tiling: CTA 128x256, BK=64, 16 k-steps; A produced in-kernel (tanh fused)
#define BM 128
#define BN 256
#define BK 64
#define NT (K_ / BK)     // 16
#define ROWB 144         // 128B payload + 16B pad (conflict-free ldmatrix)
#define A_BYTES (BM * ROWB)   // 18432
#define B_BYTES (BN * ROWB)   // 36864

// smem layout: w1 table (4KB) | b1 table (4KB) | A x2 | B x3
#define TBLW_OFF 0
#define TBLB_OFF 4096
#define A_OFF    8192
#define B_OFF    (A_OFF + 2 * A_BYTES)          // 45056
#define SMEM_BYTES (B_OFF + 3 * B_BYTES)        // 155648

// Scratch (static device globals)
__device__ __half g_Wt[P_ * K_];      // folded weights [P][K] fp16 (1MB)
__device__ float  g_bias[P_];

// ---------------------------------------------------------------------------
// helpers
// ---------------------------------------------------------------------------
__device__ __forceinline__ uint32_t smem_u32(const void* p) {
    uint32_t a;
    asm("{ .reg .u64 t; cvta.to.shared.u64 t, %1; cvt.u32.u64 %0, t; }" : "=r"(a) : "l"(p));
    return a;
}

__device__ __forceinline__ void cp16(uint32_t dst, const void* src) {
    asm volatile("cp.async.cg.shared.global [%0], [%1], 16;" :: "r"(dst), "l"(src) : "memory");
}

#define CP_COMMIT()  asm volatile("cp.async.commit_group;" ::: "memory")
#define CP_WAIT(n)   asm volatile("cp.async.wait_group %0;" :: "n"(n) : "memory")

__device__ __forceinline__ void ldmx4(uint32_t r[4], uint32_t addr) {
    asm volatile("ldmatrix.sync.aligned.m8n8.x4.shared.b16 {%0,%1,%2,%3}, [%4];"
                 : "=r"(r[0]), "=r"(r[1]), "=r"(r[2]), "=r"(r[3]) : "r"(addr));
}

__device__ __forceinline__ void mma_f16(float c[4], const uint32_t a[4], const uint32_t b0, const uint32_t b1) {
    asm volatile(
        "mma.sync.aligned.m16n8k16.row.col.f32.f16.f16.f32 "
        "{%0,%1,%2,%3}, {%4,%5,%6,%7}, {%8,%9}, {%0,%1,%2,%3};"
        : "+f"(c[0]), "+f"(c[1]), "+f"(c[2]), "+f"(c[3])
        : "r"(a[0]), "r"(a[1]), "r"(a[2]), "r"(a[3]), "r"(b0), "r"(b1));
}

__device__ __forceinline__ float tanh_fast(float x) {
    float r;
    asm("tanh.approx.f32 %0, %1;" : "=f"(r) : "f"(x));
    return r;
}

// pack two fp32 into fp16x2 (lo in low half, hi in high half)
__device__ __forceinline__ uint32_t pack_half2(float lo, float hi) {
    uint32_t r;
    asm("cvt.rn.f16x2.f32 %0, %1, %2;" : "=r"(r) : "f"(hi), "f"(lo));
    return r;
}

// ---------------------------------------------------------------------------
// Kernel 1: fold E into weights; write TRANSPOSED fp16 g_Wt[p][k]; bias
// grid 128 = (f,branch); 256 threads, each handles p and p+256
// ---------------------------------------------------------------------------
__global__ void __launch_bounds__(256) precompute_W(
        const float* __restrict__ w2v, const float* __restrict__ wx,
        const float* __restrict__ w2t, const float* __restrict__ wt,
        const float* __restrict__ bx,  const float* __restrict__ bt) {
    const int f      = blockIdx.x >> 1;
    const int branch = blockIdx.x & 1;
    const int t      = threadIdx.x;

    const float* __restrict__ w2 = branch ? w2t : w2v;
    const float* __restrict__ wp = branch ? wt  : wx;

    __shared__ float s_w2[H_ * E_];
    s_w2[t]       = w2[f * H_ * E_ + t];
    s_w2[t + 256] = w2[f * H_ * E_ + t + 256];
    __syncthreads();

    float acc0[H_], acc1[H_];
#pragma unroll
    for (int h = 0; h < H_; h++) { acc0[h] = 0.f; acc1[h] = 0.f; }

#pragma unroll 16
    for (int e = 0; e < E_; e++) {
        const float* row = wp + (size_t)(f * E_ + e) * P_;
        const float wA = row[t];
        const float wB = row[t + 256];
#pragma unroll
        for (int h = 0; h < H_; h++) {
            const float s = s_w2[h * E_ + e];
            acc0[h] = fmaf(s, wA, acc0[h]);
            acc1[h] = fmaf(s, wB, acc1[h]);
        }
    }
    uint4 st0, st1;
    st0.x = pack_half2(acc0[0], acc0[1]); st0.y = pack_half2(acc0[2], acc0[3]);
    st0.z = pack_half2(acc0[4], acc0[5]); st0.w = pack_half2(acc0[6], acc0[7]);
    st1.x = pack_half2(acc1[0], acc1[1]); st1.y = pack_half2(acc1[2], acc1[3]);
    st1.z = pack_half2(acc1[4], acc1[5]); st1.w = pack_half2(acc1[6], acc1[7]);
    const size_t koff = branch * 512 + f * H_;
    *(uint4*)&g_Wt[(size_t)t * K_ + koff]         = st0;
    *(uint4*)&g_Wt[(size_t)(t + 256) * K_ + koff] = st1;

    if (blockIdx.x == 0) {
        g_bias[t]       = bx[t]       + bt[t];
        g_bias[t + 256] = bx[t + 256] + bt[t + 256];
    }
}

// ---------------------------------------------------------------------------
// Fused GEMM: C[16384,512] = tanh(inp*w1+b1) @ Wt^T + bias
// A tiles produced in-kernel (LDG x/time -> tanh -> fp16 STS); B via cp.async.
// grid (512/BN=2, 16384/BM=128), 256 threads (8 warps: 2m x 4n), warp 64x64
// ---------------------------------------------------------------------------
__device__ __forceinline__ void fill_B(uint32_t dst, int kt, int bn, int tid) {
    const int k0 = kt * BK;
#pragma unroll
    for (int i = 0; i < 8; i++) {
        const int c   = tid + i * 256;
        const int row = c >> 3;
        const int ch  = c & 7;
        cp16(dst + (uint32_t)(row * ROWB + ch * 16),
             g_Wt + (size_t)(bn + row) * K_ + k0 + ch * 8);
    }
}

// compute one A sub-tile contribution: 4 f-values x 8 h -> 4 x 16B stores
__device__ __forceinline__ void produce_A(char* adst, const float* tblW, const float* tblB,
                                          int tb, int f0, float4 xv) {
#pragma unroll
    for (int i = 0; i < 4; i++) {
        const float xi = (&xv.x)[i];
        const float4 wl = *(const float4*)&tblW[tb + (f0 + i) * 8];
        const float4 wh = *(const float4*)&tblW[tb + (f0 + i) * 8 + 4];
        const float4 bl = *(const float4*)&tblB[tb + (f0 + i) * 8];
        const float4 bh = *(const float4*)&tblB[tb + (f0 + i) * 8 + 4];
        uint4 st;
        st.x = pack_half2(tanh_fast(fmaf(xi, wl.x, bl.x)), tanh_fast(fmaf(xi, wl.y, bl.y)));
        st.y = pack_half2(tanh_fast(fmaf(xi, wl.z, bl.z)), tanh_fast(fmaf(xi, wl.w, bl.w)));
        st.z = pack_half2(tanh_fast(fmaf(xi, wh.x, bh.x)), tanh_fast(fmaf(xi, wh.y, bh.y)));
        st.w = pack_half2(tanh_fast(fmaf(xi, wh.z, bh.z)), tanh_fast(fmaf(xi, wh.w, bh.w)));
        *(uint4*)(adst + i * 16) = st;
    }
}

__global__ void __launch_bounds__(256, 1) gemm_fused(
        float* __restrict__ C,
        const float* __restrict__ x,   const float* __restrict__ tm,
        const float* __restrict__ w1v, const float* __restrict__ b1v,
        const float* __restrict__ w1t, const float* __restrict__ b1t) {
    extern __shared__ char sm[];
    const uint32_t sbase = smem_u32(sm);
    float* tblW = (float*)(sm + TBLW_OFF);
    float* tblB = (float*)(sm + TBLB_OFF);

    const int tid  = threadIdx.x;
    const int lane = tid & 31;
    const int wid  = tid >> 5;
    const int wm   = (wid & 1) * 64;
    const int wn   = (wid >> 1) * 64;
    const int bm   = blockIdx.y * BM;
    const int bn   = blockIdx.x * BN;

    // A-producer mapping: 2 threads per row; each covers 4 f x 8 h = 32 cols
    const int arow  = tid >> 1;
    const int ahalf = tid & 1;

    // ldmatrix lane addresses (bytes within tile)
    const uint32_t a_lane = (uint32_t)((wm + (lane & 15)) * ROWB + ((lane >> 4) & 1) * 16);
    const uint32_t b_lane = (uint32_t)((wn + (lane & 7) + ((lane >> 4) & 1) * 8) * ROWB
                                       + ((lane >> 3) & 1) * 16);

    // ---- w1/b1 tables into smem ----
    for (int i = tid; i < 512; i += 256) {
        tblW[i]       = w1v[i];
        tblW[512 + i] = w1t[i];
        tblB[i]       = b1v[i];
        tblB[512 + i] = b1t[i];
    }
    __syncthreads();

    float acc[4][8][4];
#pragma unroll
    for (int mt = 0; mt < 4; mt++)
#pragma unroll
        for (int nt = 0; nt < 8; nt++)
#pragma unroll
            for (int i = 0; i < 4; i++) acc[mt][nt][i] = 0.f;

    // ---- prologue: compute A(0), start B(0), B(1) ----
    {
        const int f0 = ahalf * 4;                 // kt=0 -> branch 0, fbase 0
        const float4 xv = *(const float4*)&x[(size_t)(bm + arow) * F_ + f0];
        produce_A(sm + A_OFF + arow * ROWB + ahalf * 64, tblW, tblB, 0, f0, xv);
    }
    fill_B(sbase + B_OFF, 0, bn, tid); CP_COMMIT();
    fill_B(sbase + B_OFF + B_BYTES, 1, bn, tid); CP_COMMIT();

    int bstage = 0;
    for (int kt = 0; kt < NT; kt++) {
        CP_WAIT(1);          // my groups for B(kt) landed
        __syncthreads();     // everyone's B(kt) visible; A/B ring buffers recyclable

        const int knext = kt + 1;
        // prefetch x/time vector for A(knext) early (latency hidden under MMA)
        float4 xv = make_float4(0.f, 0.f, 0.f, 0.f);
        int f0 = 0, tb = 0;
        if (knext < NT) {
            const float* src = (knext >= 8) ? tm : x;
            tb = (knext >= 8) ? 512 : 0;
            f0 = ((knext & 7) << 3) + ahalf * 4;
            xv = *(const float4*)&src[(size_t)(bm + arow) * F_ + f0];
        }

        // refill B ring (one commit per iter keeps wait arithmetic exact)
        if (kt + 2 < NT) {
            int ns = bstage + 2; if (ns >= 3) ns -= 3;
            fill_B(sbase + B_OFF + (uint32_t)(ns * B_BYTES), kt + 2, bn, tid);
        }
        CP_COMMIT();

        // ---- MMA over A(kt&1), B(bstage) ----
        const uint32_t Abase = sbase + A_OFF + (uint32_t)((kt & 1) * A_BYTES);
        const uint32_t Bbase = sbase + B_OFF + (uint32_t)(bstage * B_BYTES);

        uint32_t a[2][4];
        uint32_t b[2][16];
#pragma unroll
        for (int np = 0; np < 4; np++)
            ldmx4(&b[0][np * 4], Bbase + b_lane + (uint32_t)(np * 16 * ROWB));
        ldmx4(a[0], Abase + a_lane);

#pragma unroll
        for (int ks = 0; ks < 4; ks++) {
            const uint32_t* bc = b[ks & 1];
            if (ks < 3) {
                uint32_t* bnx = b[(ks + 1) & 1];
#pragma unroll
                for (int np = 0; np < 4; np++)
                    ldmx4(&bnx[np * 4], Bbase + b_lane + (uint32_t)(np * 16 * ROWB + (ks + 1) * 32));
            }
#pragma unroll
            for (int mt = 0; mt < 4; mt++) {
                if (mt < 3)
                    ldmx4(a[(mt + 1) & 1], Abase + a_lane + (uint32_t)((mt + 1) * 16 * ROWB + ks * 32));
                else if (ks < 3)
                    ldmx4(a[0], Abase + a_lane + (uint32_t)((ks + 1) * 32));
                const uint32_t* ac = a[mt & 1];
#pragma unroll
                for (int nt = 0; nt < 8; nt++)
                    mma_f16(acc[mt][nt], ac, bc[nt * 2], bc[nt * 2 + 1]);
            }
        }

        // ---- produce A(knext) into the other A buffer ----
        if (knext < NT)
            produce_A(sm + A_OFF + (knext & 1) * A_BYTES + arow * ROWB + ahalf * 64,
                      tblW, tblB, tb, f0, xv);

        bstage++; if (bstage >= 3) bstage = 0;
    }

    // ---- epilogue: bias + store ----
    const int g  = lane >> 2;
    const int qc = (lane & 3) * 2;
#pragma unroll
    for (int nt = 0; nt < 8; nt++) {
        const int col = bn + wn + nt * 8 + qc;
        const float2 bias = *(const float2*)&g_bias[col];
#pragma unroll
        for (int mt = 0; mt < 4; mt++) {
            const int row = bm + wm + mt * 16 + g;
            float2 v0, v1;
            v0.x = acc[mt][nt][0] + bias.x;
            v0.y = acc[mt][nt][1] + bias.y;
            v1.x = acc[mt][nt][2] + bias.x;
            v1.y = acc[mt][nt][3] + bias.y;
            *(float2*)&C[(size_t)row * P_ + col]       = v0;
            *(float2*)&C[(size_t)(row + 8) * P_ + col] = v1;
        }
    }
}

// ---------------------------------------------------------------------------
// Launch: x, time, w1v, b1v, w2v, w1t, b1t, w2t, wx, bx, wt, bt
// ---------------------------------------------------------------------------
extern "C" void kernel_launch(void* const* d_in, const int* in_sizes, int n_in,
                              void* d_out, int out_size) {
    const float* x    = (const float*)d_in[0];
    const float* tmi  = (const float*)d_in[1];
    const float* w1v  = (const float*)d_in[2];
    const float* b1v  = (const float*)d_in[3];
    const float* w2v  = (const float*)d_in[4];
    const float* w1t  = (const float*)d_in[5];
    const float* b1t  = (const float*)d_in[6];
    const float* w2t  = (const float*)d_in[7];
    const float* wx   = (const float*)d_in[8];
    const float* bx   = (const float*)d_in[9];
    const float* wt   = (const float*)d_in[10];
    const float* bt   = (const float*)d_in[11];
    float* out = (float*)d_out;

    static bool attr_set = false;
    if (!attr_set) {
        cudaFuncSetAttribute(gemm_fused, cudaFuncAttributeMaxDynamicSharedMemorySize, SMEM_BYTES);
        attr_set = true;
    }

    precompute_W<<<128, 256>>>(w2v, wx, w2t, wt, bx, bt);
    gemm_fused<<<dim3(P_ / BN, BT_ / BM), 256, SMEM_BYTES>>>(out, x, tmi, w1v, b1v, w1t, b1t);
}